// round 7
// baseline (speedup 1.0000x reference)
#include <cuda_runtime.h>
#include <cuda_bf16.h>
#include <cstdint>
#include <math.h>

// Problem constants
#define PB 4
#define PS 2048
#define PD 1024
#define PH 16
#define PHD 64
#define M_ROWS (PB * PS)        // 8192
#define QKV_N (3 * PD)          // 3072

// 0.125 * log2(e): folded into Q so softmax uses exp2
#define QSCALE 0.18033688011112042f

// ---------------------------------------------------------------------------
// Device-global scratch (allocation-free rule)
// ---------------------------------------------------------------------------
__device__ __nv_bfloat16  g_qkvhi[M_ROWS * QKV_N];   // bf16 hi qkv
__device__ __nv_bfloat16  g_qkvlo[M_ROWS * QKV_N];   // bf16 lo qkv
__device__ __nv_bfloat16  g_xhi[M_ROWS * PD];
__device__ __nv_bfloat16  g_xlo[M_ROWS * PD];
__device__ __nv_bfloat16  g_wqkvT_hi[QKV_N * PD];    // [N,K] transposed
__device__ __nv_bfloat16  g_wqkvT_lo[QKV_N * PD];
__device__ __nv_bfloat16  g_woutT_hi[PD * PD];
__device__ __nv_bfloat16  g_woutT_lo[PD * PD];
__device__ __nv_bfloat16  g_ahi[M_ROWS * PD];        // attention out hi/lo
__device__ __nv_bfloat16  g_alo[M_ROWS * PD];

// ---------------------------------------------------------------------------
// PTX helpers (non-'a' ISA only: cp.async, ldmatrix, mma.sync)
// ---------------------------------------------------------------------------
__device__ __forceinline__ uint32_t smem_u32(const void* p) {
    uint32_t a;
    asm("{ .reg .u64 t; cvta.to.shared.u64 t, %1; cvt.u32.u64 %0, t; }"
        : "=r"(a) : "l"(p));
    return a;
}

#define CP_ASYNC16(smem, gmem) \
    asm volatile("cp.async.cg.shared.global [%0], [%1], 16;" \
                 :: "r"(smem), "l"(gmem) : "memory")
#define CP_ASYNC_COMMIT() asm volatile("cp.async.commit_group;" ::: "memory")
#define CP_ASYNC_WAIT1()  asm volatile("cp.async.wait_group 1;" ::: "memory")

__device__ __forceinline__ void ldsm_x4(uint32_t* r, uint32_t addr) {
    asm volatile("ldmatrix.sync.aligned.m8n8.x4.shared.b16 {%0,%1,%2,%3}, [%4];"
                 : "=r"(r[0]), "=r"(r[1]), "=r"(r[2]), "=r"(r[3]) : "r"(addr));
}
__device__ __forceinline__ void ldsm_x4_t(uint32_t* r, uint32_t addr) {
    asm volatile("ldmatrix.sync.aligned.m8n8.x4.trans.shared.b16 {%0,%1,%2,%3}, [%4];"
                 : "=r"(r[0]), "=r"(r[1]), "=r"(r[2]), "=r"(r[3]) : "r"(addr));
}

__device__ __forceinline__ void mma_bf16(float* c, const uint32_t* a,
                                         const uint32_t b0, const uint32_t b1) {
    asm volatile(
        "mma.sync.aligned.m16n8k16.row.col.f32.bf16.bf16.f32 "
        "{%0,%1,%2,%3}, {%4,%5,%6,%7}, {%8,%9}, {%0,%1,%2,%3};"
        : "+f"(c[0]), "+f"(c[1]), "+f"(c[2]), "+f"(c[3])
        : "r"(a[0]), "r"(a[1]), "r"(a[2]), "r"(a[3]), "r"(b0), "r"(b1));
}

__device__ __forceinline__ uint32_t pack_bf16x2(float p0, float p1) {
    __nv_bfloat162 h = __floats2bfloat162_rn(p0, p1);
    return *reinterpret_cast<uint32_t*>(&h);
}

// ---------------------------------------------------------------------------
// Prep kernels
// ---------------------------------------------------------------------------
__global__ void convert_split_kernel(const float* __restrict__ in,
                                     __nv_bfloat16* __restrict__ hi,
                                     __nv_bfloat16* __restrict__ lo, int n4) {
    int i = blockIdx.x * blockDim.x + threadIdx.x;
    if (i >= n4) return;
    float4 v = reinterpret_cast<const float4*>(in)[i];
    __nv_bfloat16 h0 = __float2bfloat16(v.x);
    __nv_bfloat16 h1 = __float2bfloat16(v.y);
    __nv_bfloat16 h2 = __float2bfloat16(v.z);
    __nv_bfloat16 h3 = __float2bfloat16(v.w);
    __nv_bfloat16 l0 = __float2bfloat16(v.x - __bfloat162float(h0));
    __nv_bfloat16 l1 = __float2bfloat16(v.y - __bfloat162float(h1));
    __nv_bfloat16 l2 = __float2bfloat16(v.z - __bfloat162float(h2));
    __nv_bfloat16 l3 = __float2bfloat16(v.w - __bfloat162float(h3));
    reinterpret_cast<__nv_bfloat162*>(hi)[i * 2 + 0] = __nv_bfloat162(h0, h1);
    reinterpret_cast<__nv_bfloat162*>(hi)[i * 2 + 1] = __nv_bfloat162(h2, h3);
    reinterpret_cast<__nv_bfloat162*>(lo)[i * 2 + 0] = __nv_bfloat162(l0, l1);
    reinterpret_cast<__nv_bfloat162*>(lo)[i * 2 + 1] = __nv_bfloat162(l2, l3);
}

// w[K][N] row-major -> wT[N][K] bf16 hi/lo
__global__ void transpose_split_kernel(const float* __restrict__ w,
                                       __nv_bfloat16* __restrict__ hiT,
                                       __nv_bfloat16* __restrict__ loT,
                                       int K, int N) {
    __shared__ float t[32][33];
    int n0 = blockIdx.x * 32, k0 = blockIdx.y * 32;
    int tx = threadIdx.x, ty = threadIdx.y;
    #pragma unroll
    for (int i = 0; i < 4; i++)
        t[ty + i * 8][tx] = w[(k0 + ty + i * 8) * N + n0 + tx];
    __syncthreads();
    #pragma unroll
    for (int i = 0; i < 4; i++) {
        int nn = ty + i * 8;
        float v = t[tx][nn];
        __nv_bfloat16 h = __float2bfloat16(v);
        __nv_bfloat16 l = __float2bfloat16(v - __bfloat162float(h));
        hiT[(size_t)(n0 + nn) * K + k0 + tx] = h;
        loT[(size_t)(n0 + nn) * K + k0 + tx] = l;
    }
}

// ---------------------------------------------------------------------------
// mma.sync split-bf16 GEMM:  C[M,N] = A[M,K] @ W[K,N] + bias
// OUTMODE 0: fp32 C.  OUTMODE 1: bf16 hi/lo C, cols<1024 scaled by QSCALE.
// BM=BN=128, BK=32, 256 thr / 8 warps, warp tile 64x32.
// Combined hi|lo rows (144 B stride: hi 64B | lo 64B | pad 16B), 3-stage
// cp.async pipeline, ONE __syncthreads per iter, 2 CTAs/SM (110.6 KB smem).
// ---------------------------------------------------------------------------
#define G_BM 128
#define G_BN 128
#define G_BK 32
#define G_STAGES 3
#define G_LDS 72                          // halves per combined row (144 B)
#define G_LOOFF 64                        // byte offset of lo half-row
#define G_TILE_H (128 * G_LDS)            // halves per matrix-pair tile (9216)
#define G_STAGE_H (2 * G_TILE_H)          // A-pair + B-pair
#define G_SMEM_BYTES (G_STAGES * G_STAGE_H * 2)   // 110592 B

__device__ __forceinline__ void gemm_load_stage(
    const __nv_bfloat16* __restrict__ Ahi, const __nv_bfloat16* __restrict__ Alo,
    const __nv_bfloat16* __restrict__ Bhi, const __nv_bfloat16* __restrict__ Blo,
    uint32_t smem_stage, int rowBlk, int colBlk, int k0, int Ktot, int tid)
{
    const __nv_bfloat16* mats[4] = {
        Ahi + (size_t)rowBlk * Ktot + k0,   // tile 0, hi
        Alo + (size_t)rowBlk * Ktot + k0,   // tile 0, lo
        Bhi + (size_t)colBlk * Ktot + k0,   // tile 1, hi
        Blo + (size_t)colBlk * Ktot + k0    // tile 1, lo
    };
    #pragma unroll
    for (int rep = 0; rep < 8; rep++) {
        int idx = tid + rep * 256;        // 0..2047
        int tile = idx >> 10;             // 0:A 1:B
        int within = idx & 1023;
        int row = within >> 3;            // 0..127
        int ch = within & 7;              // 0..3 hi chunks, 4..7 lo chunks
        const __nv_bfloat16* src =
            mats[tile * 2 + (ch >> 2)] + (size_t)row * Ktot + (ch & 3) * 8;
        uint32_t dst = smem_stage + (tile * G_TILE_H + row * G_LDS) * 2 + ch * 16;
        CP_ASYNC16(dst, src);
    }
}

template <int OUTMODE>
__global__ __launch_bounds__(256, 2) void gemm_mma_kernel(
    const __nv_bfloat16* __restrict__ Ahi, const __nv_bfloat16* __restrict__ Alo,
    const __nv_bfloat16* __restrict__ BThi, const __nv_bfloat16* __restrict__ BTlo,
    const float* __restrict__ bias, float* __restrict__ Cf,
    __nv_bfloat16* __restrict__ Chi, __nv_bfloat16* __restrict__ Clo,
    int Ktot, int Ntot)
{
    extern __shared__ __nv_bfloat16 sm[];
    const int tid = threadIdx.x;
    const int wid = tid >> 5;
    const int lane = tid & 31;
    const int wm = (wid & 1) * 64;
    const int wn = (wid >> 1) * 32;
    const int rowBlk = blockIdx.y * G_BM;
    const int colBlk = blockIdx.x * G_BN;
    const uint32_t smem_base = smem_u32(sm);

    float acc[4][4][4];
    #pragma unroll
    for (int mt = 0; mt < 4; mt++)
        #pragma unroll
        for (int nt = 0; nt < 4; nt++)
            #pragma unroll
            for (int r = 0; r < 4; r++)
                acc[mt][nt][r] = 0.0f;

    const int niter = Ktot / G_BK;

    // Prologue: stages 0, 1 in flight
    gemm_load_stage(Ahi, Alo, BThi, BTlo, smem_base, rowBlk, colBlk, 0, Ktot, tid);
    CP_ASYNC_COMMIT();
    gemm_load_stage(Ahi, Alo, BThi, BTlo, smem_base + G_STAGE_H * 2,
                    rowBlk, colBlk, G_BK, Ktot, tid);
    CP_ASYNC_COMMIT();

    int buf = 0;
    for (int i = 0; i < niter; i++) {
        CP_ASYNC_WAIT1();                 // stage i landed (i+1 may fly)
        __syncthreads();                  // publish stage i; compute(i-1) done
        // Load stage i+2 into buffer (i+2)%3 — its prior contents were
        // consumed during compute(i-1), proven finished by the sync above.
        if (i + 2 < niter) {
            int nb = buf + 2; if (nb >= G_STAGES) nb -= G_STAGES;
            gemm_load_stage(Ahi, Alo, BThi, BTlo,
                            smem_base + nb * G_STAGE_H * 2,
                            rowBlk, colBlk, (i + 2) * G_BK, Ktot, tid);
        }
        CP_ASYNC_COMMIT();                // commit every iter (group counting)

        const uint32_t stg = smem_base + buf * G_STAGE_H * 2;
        const uint32_t sA = stg;
        const uint32_t sB = stg + G_TILE_H * 2;

        #pragma unroll
        for (int ks = 0; ks < 2; ks++) {
            const uint32_t roff = (lane & 15) * (G_LDS * 2);
            const uint32_t coff = ks * 32 + (lane >> 4) * 16;   // kh*2 bytes

            uint32_t afh[4][4], afl[4][4];
            #pragma unroll
            for (int mt = 0; mt < 4; mt++) {
                uint32_t ra = sA + (wm + mt * 16) * (G_LDS * 2) + roff + coff;
                ldsm_x4(afh[mt], ra);
                ldsm_x4(afl[mt], ra + G_LOOFF);
            }
            uint32_t bfh[4][2], bfl[4][2];
            #pragma unroll
            for (int np = 0; np < 2; np++) {
                uint32_t rb = sB + (wn + np * 16) * (G_LDS * 2) + roff + coff;
                uint32_t t[4];
                ldsm_x4(t, rb);
                bfh[2 * np][0] = t[0]; bfh[2 * np][1] = t[2];
                bfh[2 * np + 1][0] = t[1]; bfh[2 * np + 1][1] = t[3];
                ldsm_x4(t, rb + G_LOOFF);
                bfl[2 * np][0] = t[0]; bfl[2 * np][1] = t[2];
                bfl[2 * np + 1][0] = t[1]; bfl[2 * np + 1][1] = t[3];
            }
            #pragma unroll
            for (int mt = 0; mt < 4; mt++)
                #pragma unroll
                for (int nt = 0; nt < 4; nt++) {
                    mma_bf16(acc[mt][nt], afh[mt], bfh[nt][0], bfh[nt][1]);
                    mma_bf16(acc[mt][nt], afh[mt], bfl[nt][0], bfl[nt][1]);
                    mma_bf16(acc[mt][nt], afl[mt], bfh[nt][0], bfh[nt][1]);
                }
        }
        buf++; if (buf >= G_STAGES) buf = 0;
    }

    // Epilogue
    #pragma unroll
    for (int mt = 0; mt < 4; mt++) {
        int row0 = rowBlk + wm + mt * 16 + (lane >> 2);
        #pragma unroll
        for (int nt = 0; nt < 4; nt++) {
            int col = colBlk + wn + nt * 8 + (lane & 3) * 2;
            float b0 = bias[col], b1 = bias[col + 1];
            float v0 = acc[mt][nt][0] + b0, v1 = acc[mt][nt][1] + b1;
            float v2 = acc[mt][nt][2] + b0, v3 = acc[mt][nt][3] + b1;
            if (OUTMODE == 0) {
                float2 w0 = { v0, v1 }, w1 = { v2, v3 };
                *reinterpret_cast<float2*>(Cf + (size_t)row0 * Ntot + col) = w0;
                *reinterpret_cast<float2*>(Cf + (size_t)(row0 + 8) * Ntot + col) = w1;
            } else {
                float sc = (col < PD) ? QSCALE : 1.0f;   // scale Q columns only
                v0 *= sc; v1 *= sc; v2 *= sc; v3 *= sc;
                __nv_bfloat16 h0 = __float2bfloat16(v0);
                __nv_bfloat16 h1 = __float2bfloat16(v1);
                __nv_bfloat16 h2 = __float2bfloat16(v2);
                __nv_bfloat16 h3 = __float2bfloat16(v3);
                __nv_bfloat16 e0 = __float2bfloat16(v0 - __bfloat162float(h0));
                __nv_bfloat16 e1 = __float2bfloat16(v1 - __bfloat162float(h1));
                __nv_bfloat16 e2 = __float2bfloat16(v2 - __bfloat162float(h2));
                __nv_bfloat16 e3 = __float2bfloat16(v3 - __bfloat162float(h3));
                *reinterpret_cast<__nv_bfloat162*>(Chi + (size_t)row0 * Ntot + col) = __nv_bfloat162(h0, h1);
                *reinterpret_cast<__nv_bfloat162*>(Chi + (size_t)(row0 + 8) * Ntot + col) = __nv_bfloat162(h2, h3);
                *reinterpret_cast<__nv_bfloat162*>(Clo + (size_t)row0 * Ntot + col) = __nv_bfloat162(e0, e1);
                *reinterpret_cast<__nv_bfloat162*>(Clo + (size_t)(row0 + 8) * Ntot + col) = __nv_bfloat162(e2, e3);
            }
        }
    }
}

// ---------------------------------------------------------------------------
// Tensor-core flash attention (causal, split-bf16, online softmax base-2).
// Br=128, Bc=64, 256 thr / 8 warps (m16 per warp). Q pre-scaled by QSCALE.
// 3-stage cp.async KV pipeline. Emits bf16 hi/lo for the out projection.
// (unchanged from round 6)
// ---------------------------------------------------------------------------
#define F_LDS 72                           // halves; 144 B row stride
#define F_QTILE (128 * F_LDS)              // halves per Q matrix (9216)
#define F_KVT (64 * F_LDS)                 // halves per KV matrix (4608)
#define F_SMEM_BYTES ((2 * F_QTILE + 3 * 4 * F_KVT) * 2)   // 147456 B

__device__ __forceinline__ void flash_load_kv(
    const __nv_bfloat16* __restrict__ qhi, const __nv_bfloat16* __restrict__ qlo,
    uint32_t stage, int b, int h, int j0, int tid)
{
    #pragma unroll
    for (int rep = 0; rep < 8; rep++) {
        int idx = tid + rep * 256;        // 0..2047
        int mat = idx >> 9;               // 0:Khi 1:Klo 2:Vhi 3:Vlo
        int row = (idx >> 3) & 63;
        int ch = idx & 7;
        const __nv_bfloat16* base = (mat & 1) ? qlo : qhi;
        int colbase = (mat >> 1) ? 2 * PD : PD;   // V : K
        const __nv_bfloat16* src = base +
            (size_t)(b * PS + j0 + row) * QKV_N + colbase + h * PHD + ch * 8;
        uint32_t dst = stage + (mat * F_KVT + row * F_LDS + ch * 8) * 2;
        CP_ASYNC16(dst, src);
    }
}

__global__ __launch_bounds__(256) void flash_mma_kernel(
    const __nv_bfloat16* __restrict__ qhi, const __nv_bfloat16* __restrict__ qlo,
    __nv_bfloat16* __restrict__ out_hi, __nv_bfloat16* __restrict__ out_lo)
{
    extern __shared__ __nv_bfloat16 fsm[];
    const int tid = threadIdx.x;
    const int lane = tid & 31;
    const int wid = tid >> 5;
    const int wm = wid * 16;
    const int bh = blockIdx.y;
    const int b = bh >> 4;
    const int h = bh & 15;
    const int q0 = blockIdx.x * 128;

    const uint32_t sb = smem_u32(fsm);
    const uint32_t sQh = sb, sQl = sb + F_QTILE * 2;
    const uint32_t kvbase = sb + 2 * F_QTILE * 2;

    // Prologue: Q tile + KV stage 0 (group), KV stage 1 (group)
    #pragma unroll
    for (int rep = 0; rep < 8; rep++) {
        int idx = tid + rep * 256;        // 0..2047
        int mat = idx >> 10;              // 0:Qhi 1:Qlo
        int row = (idx >> 3) & 127;
        int ch = idx & 7;
        const __nv_bfloat16* src = (mat ? qlo : qhi) +
            (size_t)(b * PS + q0 + row) * QKV_N + h * PHD + ch * 8;
        uint32_t dst = (mat ? sQl : sQh) + (row * F_LDS + ch * 8) * 2;
        CP_ASYNC16(dst, src);
    }
    flash_load_kv(qhi, qlo, kvbase, b, h, 0, tid);
    CP_ASYNC_COMMIT();
    const int ntiles = (q0 + 128) / 64;   // >= 2
    flash_load_kv(qhi, qlo, kvbase + 4 * F_KVT * 2, b, h, 64, tid);
    CP_ASYNC_COMMIT();

    uint32_t qfh[4][4], qfl[4][4];        // Q A-frags (4 k16 groups)
    float of[8][4];
    #pragma unroll
    for (int nt = 0; nt < 8; nt++)
        #pragma unroll
        for (int r = 0; r < 4; r++) of[nt][r] = 0.0f;
    float m_a = -1e30f, m_b = -1e30f, l_a = 0.0f, l_b = 0.0f;

    const uint32_t roff = (lane & 15) * (F_LDS * 2);
    const uint32_t coff = (lane >> 4) * 8 * 2;

    for (int i = 0; i < ntiles; i++) {
        CP_ASYNC_WAIT1();
        __syncthreads();

        if (i == 0) {                     // Q frags once (stage0 group incl. Q)
            #pragma unroll
            for (int g = 0; g < 4; g++) {
                uint32_t ra = wm * (F_LDS * 2) + roff + coff + g * 32;  // col g*16
                ldsm_x4(qfh[g], sQh + ra);
                ldsm_x4(qfl[g], sQl + ra);
            }
        }
        if (i + 2 < ntiles)
            flash_load_kv(qhi, qlo, kvbase + ((i + 2) % 3) * 4 * F_KVT * 2,
                          b, h, (i + 2) * 64, tid);
        CP_ASYNC_COMMIT();

        const uint32_t stg = kvbase + (i % 3) * 4 * F_KVT * 2;
        const uint32_t sKh = stg, sKl = stg + F_KVT * 2;
        const uint32_t sVh = stg + 2 * F_KVT * 2, sVl = stg + 3 * F_KVT * 2;
        const int j0 = i * 64;

        // ---- scores S = Q @ K^T (3-term split) ----
        float sf[8][4];
        #pragma unroll
        for (int nt = 0; nt < 8; nt++)
            #pragma unroll
            for (int r = 0; r < 4; r++) sf[nt][r] = 0.0f;

        #pragma unroll
        for (int kk = 0; kk < 4; kk++) {
            uint32_t ck = coff + kk * 32;             // hd col = kk*16 + ...
            uint32_t bkh[8][2], bkl[8][2];
            #pragma unroll
            for (int np = 0; np < 4; np++) {          // kv n16 groups
                uint32_t rb = (np * 16) * (F_LDS * 2) + roff + ck;
                uint32_t t[4];
                ldsm_x4(t, sKh + rb);
                bkh[2 * np][0] = t[0]; bkh[2 * np][1] = t[2];
                bkh[2 * np + 1][0] = t[1]; bkh[2 * np + 1][1] = t[3];
                ldsm_x4(t, sKl + rb);
                bkl[2 * np][0] = t[0]; bkl[2 * np][1] = t[2];
                bkl[2 * np + 1][0] = t[1]; bkl[2 * np + 1][1] = t[3];
            }
            #pragma unroll
            for (int nt = 0; nt < 8; nt++) {
                mma_bf16(sf[nt], qfh[kk], bkh[nt][0], bkh[nt][1]);
                mma_bf16(sf[nt], qfh[kk], bkl[nt][0], bkl[nt][1]);
                mma_bf16(sf[nt], qfl[kk], bkh[nt][0], bkh[nt][1]);
            }
        }

        // ---- causal mask (only the last two tiles touch the diagonal) ----
        const int r_a = q0 + wm + (lane >> 2);
        if (i >= ntiles - 2) {
            #pragma unroll
            for (int nt = 0; nt < 8; nt++) {
                int c0 = j0 + nt * 8 + (lane & 3) * 2;
                if (c0 > r_a)     sf[nt][0] = -1e30f;
                if (c0 + 1 > r_a) sf[nt][1] = -1e30f;
                if (c0 > r_a + 8)     sf[nt][2] = -1e30f;
                if (c0 + 1 > r_a + 8) sf[nt][3] = -1e30f;
            }
        }

        // ---- online softmax (base-2 domain; QSCALE folded into Q) ----
        float tm_a = -1e30f, tm_b = -1e30f;
        #pragma unroll
        for (int nt = 0; nt < 8; nt++) {
            tm_a = fmaxf(tm_a, fmaxf(sf[nt][0], sf[nt][1]));
            tm_b = fmaxf(tm_b, fmaxf(sf[nt][2], sf[nt][3]));
        }
        tm_a = fmaxf(tm_a, __shfl_xor_sync(0xffffffffu, tm_a, 1));
        tm_a = fmaxf(tm_a, __shfl_xor_sync(0xffffffffu, tm_a, 2));
        tm_b = fmaxf(tm_b, __shfl_xor_sync(0xffffffffu, tm_b, 1));
        tm_b = fmaxf(tm_b, __shfl_xor_sync(0xffffffffu, tm_b, 2));

        float mn_a = fmaxf(m_a, tm_a), mn_b = fmaxf(m_b, tm_b);
        float alpha_a = exp2f(m_a - mn_a), alpha_b = exp2f(m_b - mn_b);
        m_a = mn_a; m_b = mn_b;
        l_a *= alpha_a; l_b *= alpha_b;
        #pragma unroll
        for (int nt = 0; nt < 8; nt++) {
            of[nt][0] *= alpha_a; of[nt][1] *= alpha_a;
            of[nt][2] *= alpha_b; of[nt][3] *= alpha_b;
        }

        float rs_a = 0.0f, rs_b = 0.0f;
        #pragma unroll
        for (int nt = 0; nt < 8; nt++) {
            sf[nt][0] = exp2f(sf[nt][0] - m_a);
            sf[nt][1] = exp2f(sf[nt][1] - m_a);
            sf[nt][2] = exp2f(sf[nt][2] - m_b);
            sf[nt][3] = exp2f(sf[nt][3] - m_b);
            rs_a += sf[nt][0] + sf[nt][1];
            rs_b += sf[nt][2] + sf[nt][3];
        }
        rs_a += __shfl_xor_sync(0xffffffffu, rs_a, 1);
        rs_a += __shfl_xor_sync(0xffffffffu, rs_a, 2);
        rs_b += __shfl_xor_sync(0xffffffffu, rs_b, 1);
        rs_b += __shfl_xor_sync(0xffffffffu, rs_b, 2);
        l_a += rs_a; l_b += rs_b;

        // ---- pack P into A-frags (hi + residual lo) ----
        uint32_t pfh[4][4], pfl[4][4];
        #pragma unroll
        for (int g = 0; g < 4; g++) {
            #pragma unroll
            for (int q = 0; q < 4; q++) {
                int f = 2 * g + (q >> 1);
                int e = (q & 1) * 2;
                float p0 = sf[f][e], p1 = sf[f][e + 1];
                uint32_t u = pack_bf16x2(p0, p1);
                pfh[g][q] = u;
                float h0 = __uint_as_float(u << 16);
                float h1 = __uint_as_float(u & 0xffff0000u);
                pfl[g][q] = pack_bf16x2(p0 - h0, p1 - h1);
            }
        }

        // ---- O += P @ V (3-term split), V via ldmatrix.trans ----
        #pragma unroll
        for (int g = 0; g < 4; g++) {                 // kv k16 groups
            uint32_t bvh[8][2], bvl[8][2];
            #pragma unroll
            for (int hh = 0; hh < 4; hh++) {          // hd n16 groups
                uint32_t rb = (g * 16) * (F_LDS * 2) + roff + coff + hh * 32;
                uint32_t t[4];
                ldsm_x4_t(t, sVh + rb);
                bvh[2 * hh][0] = t[0]; bvh[2 * hh][1] = t[1];
                bvh[2 * hh + 1][0] = t[2]; bvh[2 * hh + 1][1] = t[3];
                ldsm_x4_t(t, sVl + rb);
                bvl[2 * hh][0] = t[0]; bvl[2 * hh][1] = t[1];
                bvl[2 * hh + 1][0] = t[2]; bvl[2 * hh + 1][1] = t[3];
            }
            #pragma unroll
            for (int nt = 0; nt < 8; nt++) {
                mma_bf16(of[nt], pfh[g], bvh[nt][0], bvh[nt][1]);
                mma_bf16(of[nt], pfh[g], bvl[nt][0], bvl[nt][1]);
                mma_bf16(of[nt], pfl[g], bvh[nt][0], bvh[nt][1]);
            }
        }
        __syncthreads();
    }

    // ---- epilogue: normalize, split to bf16 hi/lo, store ----
    const float inva = 1.0f / l_a, invb = 1.0f / l_b;
    const size_t row_a = (size_t)(b * PS + q0 + wm + (lane >> 2));
    #pragma unroll
    for (int nt = 0; nt < 8; nt++) {
        int col = h * PHD + nt * 8 + (lane & 3) * 2;
        float v0 = of[nt][0] * inva, v1 = of[nt][1] * inva;
        float v2 = of[nt][2] * invb, v3 = of[nt][3] * invb;
        __nv_bfloat16 h0 = __float2bfloat16(v0), h1 = __float2bfloat16(v1);
        __nv_bfloat16 h2 = __float2bfloat16(v2), h3 = __float2bfloat16(v3);
        __nv_bfloat16 e0 = __float2bfloat16(v0 - __bfloat162float(h0));
        __nv_bfloat16 e1 = __float2bfloat16(v1 - __bfloat162float(h1));
        __nv_bfloat16 e2 = __float2bfloat16(v2 - __bfloat162float(h2));
        __nv_bfloat16 e3 = __float2bfloat16(v3 - __bfloat162float(h3));
        *reinterpret_cast<__nv_bfloat162*>(out_hi + row_a * PD + col) = __nv_bfloat162(h0, h1);
        *reinterpret_cast<__nv_bfloat162*>(out_hi + (row_a + 8) * PD + col) = __nv_bfloat162(h2, h3);
        *reinterpret_cast<__nv_bfloat162*>(out_lo + row_a * PD + col) = __nv_bfloat162(e0, e1);
        *reinterpret_cast<__nv_bfloat162*>(out_lo + (row_a + 8) * PD + col) = __nv_bfloat162(e2, e3);
    }
}

// ---------------------------------------------------------------------------
// Launch
// ---------------------------------------------------------------------------
extern "C" void kernel_launch(void* const* d_in, const int* in_sizes, int n_in,
                              void* d_out, int out_size)
{
    const float* x     = (const float*)d_in[0];
    const float* w_qkv = (const float*)d_in[1];
    const float* b_qkv = (const float*)d_in[2];
    const float* w_out = (const float*)d_in[3];
    const float* b_out = (const float*)d_in[4];
    float* out = (float*)d_out;

    __nv_bfloat16 *qkvhi, *qkvlo, *xhi, *xlo, *wqh, *wql, *woh, *wol, *ahi, *alo;
    cudaGetSymbolAddress((void**)&qkvhi, g_qkvhi);
    cudaGetSymbolAddress((void**)&qkvlo, g_qkvlo);
    cudaGetSymbolAddress((void**)&xhi, g_xhi);
    cudaGetSymbolAddress((void**)&xlo, g_xlo);
    cudaGetSymbolAddress((void**)&wqh, g_wqkvT_hi);
    cudaGetSymbolAddress((void**)&wql, g_wqkvT_lo);
    cudaGetSymbolAddress((void**)&woh, g_woutT_hi);
    cudaGetSymbolAddress((void**)&wol, g_woutT_lo);
    cudaGetSymbolAddress((void**)&ahi, g_ahi);
    cudaGetSymbolAddress((void**)&alo, g_alo);

    cudaFuncSetAttribute(gemm_mma_kernel<0>,
                         cudaFuncAttributeMaxDynamicSharedMemorySize, G_SMEM_BYTES);
    cudaFuncSetAttribute(gemm_mma_kernel<1>,
                         cudaFuncAttributeMaxDynamicSharedMemorySize, G_SMEM_BYTES);
    cudaFuncSetAttribute(flash_mma_kernel,
                         cudaFuncAttributeMaxDynamicSharedMemorySize, F_SMEM_BYTES);

    // Prep: split x; transpose+split weights
    {
        int n4 = M_ROWS * PD / 4;
        convert_split_kernel<<<(n4 + 255) / 256, 256>>>(x, xhi, xlo, n4);
        dim3 blk(32, 8);
        transpose_split_kernel<<<dim3(QKV_N / 32, PD / 32), blk>>>(w_qkv, wqh, wql, PD, QKV_N);
        transpose_split_kernel<<<dim3(PD / 32, PD / 32), blk>>>(w_out, woh, wol, PD, PD);
    }

    // 1) QKV projection -> bf16 hi/lo (Q columns pre-scaled by 0.125*log2e)
    {
        dim3 grid(QKV_N / G_BN, M_ROWS / G_BM);
        gemm_mma_kernel<1><<<grid, 256, G_SMEM_BYTES>>>(xhi, xlo, wqh, wql,
                                                        b_qkv, nullptr, qkvhi, qkvlo,
                                                        PD, QKV_N);
    }

    // 2) Tensor-core causal flash attention -> bf16 hi/lo
    {
        dim3 grid(PS / 128, PB * PH);             // (16, 64)
        flash_mma_kernel<<<grid, 256, F_SMEM_BYTES>>>(qkvhi, qkvlo, ahi, alo);
    }

    // 3) Output projection -> fp32 out
    {
        dim3 grid(PD / G_BN, M_ROWS / G_BM);
        gemm_mma_kernel<0><<<grid, 256, G_SMEM_BYTES>>>(ahi, alo, woh, wol,
                                                        b_out, out, nullptr, nullptr,
                                                        PD, PD);
    }
}

// round 8
// speedup vs baseline: 1.0077x; 1.0077x over previous
#include <cuda_runtime.h>
#include <cuda_bf16.h>
#include <cstdint>
#include <math.h>

// Problem constants
#define PB 4
#define PS 2048
#define PD 1024
#define PH 16
#define PHD 64
#define M_ROWS (PB * PS)        // 8192
#define QKV_N (3 * PD)          // 3072

// 0.125 * log2(e): folded into Q so softmax uses exp2
#define QSCALE 0.18033688011112042f

// ---------------------------------------------------------------------------
// Device-global scratch (allocation-free rule)
// ---------------------------------------------------------------------------
__device__ __nv_bfloat16  g_qkvhi[M_ROWS * QKV_N];   // bf16 hi qkv
__device__ __nv_bfloat16  g_qkvlo[M_ROWS * QKV_N];   // bf16 lo qkv
__device__ __nv_bfloat16  g_xhi[M_ROWS * PD];
__device__ __nv_bfloat16  g_xlo[M_ROWS * PD];
__device__ __nv_bfloat16  g_wqkvT_hi[QKV_N * PD];    // [N,K] transposed
__device__ __nv_bfloat16  g_wqkvT_lo[QKV_N * PD];
__device__ __nv_bfloat16  g_woutT_hi[PD * PD];
__device__ __nv_bfloat16  g_woutT_lo[PD * PD];
__device__ __nv_bfloat16  g_ahi[M_ROWS * PD];        // attention out hi/lo
__device__ __nv_bfloat16  g_alo[M_ROWS * PD];

// ---------------------------------------------------------------------------
// PTX helpers (non-'a' ISA only: cp.async, ldmatrix, mma.sync)
// ---------------------------------------------------------------------------
__device__ __forceinline__ uint32_t smem_u32(const void* p) {
    uint32_t a;
    asm("{ .reg .u64 t; cvta.to.shared.u64 t, %1; cvt.u32.u64 %0, t; }"
        : "=r"(a) : "l"(p));
    return a;
}

#define CP_ASYNC16(smem, gmem) \
    asm volatile("cp.async.cg.shared.global [%0], [%1], 16;" \
                 :: "r"(smem), "l"(gmem) : "memory")
#define CP_ASYNC_COMMIT() asm volatile("cp.async.commit_group;" ::: "memory")
#define CP_ASYNC_WAIT1()  asm volatile("cp.async.wait_group 1;" ::: "memory")

__device__ __forceinline__ void ldsm_x4(uint32_t* r, uint32_t addr) {
    asm volatile("ldmatrix.sync.aligned.m8n8.x4.shared.b16 {%0,%1,%2,%3}, [%4];"
                 : "=r"(r[0]), "=r"(r[1]), "=r"(r[2]), "=r"(r[3]) : "r"(addr));
}
__device__ __forceinline__ void ldsm_x4_t(uint32_t* r, uint32_t addr) {
    asm volatile("ldmatrix.sync.aligned.m8n8.x4.trans.shared.b16 {%0,%1,%2,%3}, [%4];"
                 : "=r"(r[0]), "=r"(r[1]), "=r"(r[2]), "=r"(r[3]) : "r"(addr));
}

__device__ __forceinline__ void mma_bf16(float* c, const uint32_t* a,
                                         const uint32_t b0, const uint32_t b1) {
    asm volatile(
        "mma.sync.aligned.m16n8k16.row.col.f32.bf16.bf16.f32 "
        "{%0,%1,%2,%3}, {%4,%5,%6,%7}, {%8,%9}, {%0,%1,%2,%3};"
        : "+f"(c[0]), "+f"(c[1]), "+f"(c[2]), "+f"(c[3])
        : "r"(a[0]), "r"(a[1]), "r"(a[2]), "r"(a[3]), "r"(b0), "r"(b1));
}

__device__ __forceinline__ uint32_t pack_bf16x2(float p0, float p1) {
    __nv_bfloat162 h = __floats2bfloat162_rn(p0, p1);
    return *reinterpret_cast<uint32_t*>(&h);
}

// ---------------------------------------------------------------------------
// Prep kernels
// ---------------------------------------------------------------------------
__global__ void convert_split_kernel(const float* __restrict__ in,
                                     __nv_bfloat16* __restrict__ hi,
                                     __nv_bfloat16* __restrict__ lo, int n4) {
    int i = blockIdx.x * blockDim.x + threadIdx.x;
    if (i >= n4) return;
    float4 v = reinterpret_cast<const float4*>(in)[i];
    __nv_bfloat16 h0 = __float2bfloat16(v.x);
    __nv_bfloat16 h1 = __float2bfloat16(v.y);
    __nv_bfloat16 h2 = __float2bfloat16(v.z);
    __nv_bfloat16 h3 = __float2bfloat16(v.w);
    __nv_bfloat16 l0 = __float2bfloat16(v.x - __bfloat162float(h0));
    __nv_bfloat16 l1 = __float2bfloat16(v.y - __bfloat162float(h1));
    __nv_bfloat16 l2 = __float2bfloat16(v.z - __bfloat162float(h2));
    __nv_bfloat16 l3 = __float2bfloat16(v.w - __bfloat162float(h3));
    reinterpret_cast<__nv_bfloat162*>(hi)[i * 2 + 0] = __nv_bfloat162(h0, h1);
    reinterpret_cast<__nv_bfloat162*>(hi)[i * 2 + 1] = __nv_bfloat162(h2, h3);
    reinterpret_cast<__nv_bfloat162*>(lo)[i * 2 + 0] = __nv_bfloat162(l0, l1);
    reinterpret_cast<__nv_bfloat162*>(lo)[i * 2 + 1] = __nv_bfloat162(l2, l3);
}

// w[K][N] row-major -> wT[N][K] bf16 hi/lo
__global__ void transpose_split_kernel(const float* __restrict__ w,
                                       __nv_bfloat16* __restrict__ hiT,
                                       __nv_bfloat16* __restrict__ loT,
                                       int K, int N) {
    __shared__ float t[32][33];
    int n0 = blockIdx.x * 32, k0 = blockIdx.y * 32;
    int tx = threadIdx.x, ty = threadIdx.y;
    #pragma unroll
    for (int i = 0; i < 4; i++)
        t[ty + i * 8][tx] = w[(k0 + ty + i * 8) * N + n0 + tx];
    __syncthreads();
    #pragma unroll
    for (int i = 0; i < 4; i++) {
        int nn = ty + i * 8;
        float v = t[tx][nn];
        __nv_bfloat16 h = __float2bfloat16(v);
        __nv_bfloat16 l = __float2bfloat16(v - __bfloat162float(h));
        hiT[(size_t)(n0 + nn) * K + k0 + tx] = h;
        loT[(size_t)(n0 + nn) * K + k0 + tx] = l;
    }
}

// ---------------------------------------------------------------------------
// mma.sync split-bf16 GEMM:  C[M,N] = A[M,K] @ W[K,N] + bias
// OUTMODE 0: fp32 C.  OUTMODE 1: bf16 hi/lo C, cols<1024 scaled by QSCALE.
// BM=BN=128, BK=32, 256 thr / 8 warps, warp tile 64x32.
// Combined hi|lo rows (144 B stride). 3-stage cp.async pipeline, one sync
// per iter, 2 CTAs/SM. Inner loop is TERM-ORDERED with A-frag register
// reuse (hi MMAs consume A-hi, then A-lo overwrites the same regs) to keep
// live registers well under the 128 cap.
// ---------------------------------------------------------------------------
#define G_BM 128
#define G_BN 128
#define G_BK 32
#define G_STAGES 3
#define G_LDS 72                          // halves per combined row (144 B)
#define G_LOOFF 64                        // byte offset of lo half-row
#define G_TILE_H (128 * G_LDS)            // halves per matrix-pair tile (9216)
#define G_STAGE_H (2 * G_TILE_H)          // A-pair + B-pair
#define G_SMEM_BYTES (G_STAGES * G_STAGE_H * 2)   // 110592 B

__device__ __forceinline__ void gemm_load_stage(
    const __nv_bfloat16* __restrict__ Ahi, const __nv_bfloat16* __restrict__ Alo,
    const __nv_bfloat16* __restrict__ Bhi, const __nv_bfloat16* __restrict__ Blo,
    uint32_t smem_stage, int rowBlk, int colBlk, int k0, int Ktot, int tid)
{
    const __nv_bfloat16* mats[4] = {
        Ahi + (size_t)rowBlk * Ktot + k0,   // tile 0, hi
        Alo + (size_t)rowBlk * Ktot + k0,   // tile 0, lo
        Bhi + (size_t)colBlk * Ktot + k0,   // tile 1, hi
        Blo + (size_t)colBlk * Ktot + k0    // tile 1, lo
    };
    #pragma unroll
    for (int rep = 0; rep < 8; rep++) {
        int idx = tid + rep * 256;        // 0..2047
        int tile = idx >> 10;             // 0:A 1:B
        int within = idx & 1023;
        int row = within >> 3;            // 0..127
        int ch = within & 7;              // 0..3 hi chunks, 4..7 lo chunks
        const __nv_bfloat16* src =
            mats[tile * 2 + (ch >> 2)] + (size_t)row * Ktot + (ch & 3) * 8;
        uint32_t dst = smem_stage + (tile * G_TILE_H + row * G_LDS) * 2 + ch * 16;
        CP_ASYNC16(dst, src);
    }
}

template <int OUTMODE>
__global__ __launch_bounds__(256, 2) void gemm_mma_kernel(
    const __nv_bfloat16* __restrict__ Ahi, const __nv_bfloat16* __restrict__ Alo,
    const __nv_bfloat16* __restrict__ BThi, const __nv_bfloat16* __restrict__ BTlo,
    const float* __restrict__ bias, float* __restrict__ Cf,
    __nv_bfloat16* __restrict__ Chi, __nv_bfloat16* __restrict__ Clo,
    int Ktot, int Ntot)
{
    extern __shared__ __nv_bfloat16 sm[];
    const int tid = threadIdx.x;
    const int wid = tid >> 5;
    const int lane = tid & 31;
    const int wm = (wid & 1) * 64;
    const int wn = (wid >> 1) * 32;
    const int rowBlk = blockIdx.y * G_BM;
    const int colBlk = blockIdx.x * G_BN;
    const uint32_t smem_base = smem_u32(sm);

    // Invariant parts of the ldmatrix addresses (hoisted out of the loop)
    const uint32_t lrow = (lane & 15) * (G_LDS * 2) + (lane >> 4) * 16;
    const uint32_t aoff = wm * (G_LDS * 2) + lrow;                 // + stg
    const uint32_t boff = G_TILE_H * 2 + wn * (G_LDS * 2) + lrow;  // + stg

    float acc[4][4][4];
    #pragma unroll
    for (int mt = 0; mt < 4; mt++)
        #pragma unroll
        for (int nt = 0; nt < 4; nt++)
            #pragma unroll
            for (int r = 0; r < 4; r++)
                acc[mt][nt][r] = 0.0f;

    const int niter = Ktot / G_BK;

    // Prologue: stages 0, 1 in flight
    gemm_load_stage(Ahi, Alo, BThi, BTlo, smem_base, rowBlk, colBlk, 0, Ktot, tid);
    CP_ASYNC_COMMIT();
    gemm_load_stage(Ahi, Alo, BThi, BTlo, smem_base + G_STAGE_H * 2,
                    rowBlk, colBlk, G_BK, Ktot, tid);
    CP_ASYNC_COMMIT();

    int buf = 0;
    for (int i = 0; i < niter; i++) {
        CP_ASYNC_WAIT1();                 // stage i landed (i+1 may fly)
        __syncthreads();                  // publish stage i; compute(i-1) done
        if (i + 2 < niter) {
            int nb = buf + 2; if (nb >= G_STAGES) nb -= G_STAGES;
            gemm_load_stage(Ahi, Alo, BThi, BTlo,
                            smem_base + nb * G_STAGE_H * 2,
                            rowBlk, colBlk, (i + 2) * G_BK, Ktot, tid);
        }
        CP_ASYNC_COMMIT();                // commit every iter (group counting)

        const uint32_t stg = smem_base + buf * G_STAGE_H * 2;

        #pragma unroll
        for (int ks = 0; ks < 2; ks++) {
            const uint32_t ck = ks * 32;

            // B fragments: hi and lo (16 regs live)
            uint32_t bh[4][2], bl[4][2];
            #pragma unroll
            for (int np = 0; np < 2; np++) {
                uint32_t rb = stg + boff + np * 16 * (G_LDS * 2) + ck;
                uint32_t t[4];
                ldsm_x4(t, rb);
                bh[2 * np][0] = t[0]; bh[2 * np][1] = t[2];
                bh[2 * np + 1][0] = t[1]; bh[2 * np + 1][1] = t[3];
                ldsm_x4(t, rb + G_LOOFF);
                bl[2 * np][0] = t[0]; bl[2 * np][1] = t[2];
                bl[2 * np + 1][0] = t[1]; bl[2 * np + 1][1] = t[3];
            }

            // A fragments: hi first (16 regs), run hi*hi and hi*lo terms
            uint32_t af[4][4];
            #pragma unroll
            for (int mt = 0; mt < 4; mt++)
                ldsm_x4(af[mt], stg + aoff + mt * 16 * (G_LDS * 2) + ck);
            #pragma unroll
            for (int mt = 0; mt < 4; mt++)
                #pragma unroll
                for (int nt = 0; nt < 4; nt++) {
                    mma_bf16(acc[mt][nt], af[mt], bh[nt][0], bh[nt][1]);
                    mma_bf16(acc[mt][nt], af[mt], bl[nt][0], bl[nt][1]);
                }

            // A-lo overwrites the same frag registers, run lo*hi term
            #pragma unroll
            for (int mt = 0; mt < 4; mt++)
                ldsm_x4(af[mt], stg + aoff + mt * 16 * (G_LDS * 2) + ck + G_LOOFF);
            #pragma unroll
            for (int mt = 0; mt < 4; mt++)
                #pragma unroll
                for (int nt = 0; nt < 4; nt++)
                    mma_bf16(acc[mt][nt], af[mt], bh[nt][0], bh[nt][1]);
        }
        buf++; if (buf >= G_STAGES) buf = 0;
    }

    // Epilogue
    #pragma unroll
    for (int mt = 0; mt < 4; mt++) {
        int row0 = rowBlk + wm + mt * 16 + (lane >> 2);
        #pragma unroll
        for (int nt = 0; nt < 4; nt++) {
            int col = colBlk + wn + nt * 8 + (lane & 3) * 2;
            float b0 = bias[col], b1 = bias[col + 1];
            float v0 = acc[mt][nt][0] + b0, v1 = acc[mt][nt][1] + b1;
            float v2 = acc[mt][nt][2] + b0, v3 = acc[mt][nt][3] + b1;
            if (OUTMODE == 0) {
                float2 w0 = { v0, v1 }, w1 = { v2, v3 };
                *reinterpret_cast<float2*>(Cf + (size_t)row0 * Ntot + col) = w0;
                *reinterpret_cast<float2*>(Cf + (size_t)(row0 + 8) * Ntot + col) = w1;
            } else {
                float sc = (col < PD) ? QSCALE : 1.0f;   // scale Q columns only
                v0 *= sc; v1 *= sc; v2 *= sc; v3 *= sc;
                __nv_bfloat16 h0 = __float2bfloat16(v0);
                __nv_bfloat16 h1 = __float2bfloat16(v1);
                __nv_bfloat16 h2 = __float2bfloat16(v2);
                __nv_bfloat16 h3 = __float2bfloat16(v3);
                __nv_bfloat16 e0 = __float2bfloat16(v0 - __bfloat162float(h0));
                __nv_bfloat16 e1 = __float2bfloat16(v1 - __bfloat162float(h1));
                __nv_bfloat16 e2 = __float2bfloat16(v2 - __bfloat162float(h2));
                __nv_bfloat16 e3 = __float2bfloat16(v3 - __bfloat162float(h3));
                *reinterpret_cast<__nv_bfloat162*>(Chi + (size_t)row0 * Ntot + col) = __nv_bfloat162(h0, h1);
                *reinterpret_cast<__nv_bfloat162*>(Chi + (size_t)(row0 + 8) * Ntot + col) = __nv_bfloat162(h2, h3);
                *reinterpret_cast<__nv_bfloat162*>(Clo + (size_t)row0 * Ntot + col) = __nv_bfloat162(e0, e1);
                *reinterpret_cast<__nv_bfloat162*>(Clo + (size_t)(row0 + 8) * Ntot + col) = __nv_bfloat162(e2, e3);
            }
        }
    }
}

// ---------------------------------------------------------------------------
// Tensor-core flash attention (causal, split-bf16, online softmax base-2).
// Br=128, Bc=64, 256 thr / 8 warps (m16 per warp). Q pre-scaled by QSCALE.
// 3-stage cp.async KV pipeline. Emits bf16 hi/lo for the out projection.
// (unchanged)
// ---------------------------------------------------------------------------
#define F_LDS 72                           // halves; 144 B row stride
#define F_QTILE (128 * F_LDS)              // halves per Q matrix (9216)
#define F_KVT (64 * F_LDS)                 // halves per KV matrix (4608)
#define F_SMEM_BYTES ((2 * F_QTILE + 3 * 4 * F_KVT) * 2)   // 147456 B

__device__ __forceinline__ void flash_load_kv(
    const __nv_bfloat16* __restrict__ qhi, const __nv_bfloat16* __restrict__ qlo,
    uint32_t stage, int b, int h, int j0, int tid)
{
    #pragma unroll
    for (int rep = 0; rep < 8; rep++) {
        int idx = tid + rep * 256;        // 0..2047
        int mat = idx >> 9;               // 0:Khi 1:Klo 2:Vhi 3:Vlo
        int row = (idx >> 3) & 63;
        int ch = idx & 7;
        const __nv_bfloat16* base = (mat & 1) ? qlo : qhi;
        int colbase = (mat >> 1) ? 2 * PD : PD;   // V : K
        const __nv_bfloat16* src = base +
            (size_t)(b * PS + j0 + row) * QKV_N + colbase + h * PHD + ch * 8;
        uint32_t dst = stage + (mat * F_KVT + row * F_LDS + ch * 8) * 2;
        CP_ASYNC16(dst, src);
    }
}

__global__ __launch_bounds__(256) void flash_mma_kernel(
    const __nv_bfloat16* __restrict__ qhi, const __nv_bfloat16* __restrict__ qlo,
    __nv_bfloat16* __restrict__ out_hi, __nv_bfloat16* __restrict__ out_lo)
{
    extern __shared__ __nv_bfloat16 fsm[];
    const int tid = threadIdx.x;
    const int lane = tid & 31;
    const int wid = tid >> 5;
    const int wm = wid * 16;
    const int bh = blockIdx.y;
    const int b = bh >> 4;
    const int h = bh & 15;
    const int q0 = blockIdx.x * 128;

    const uint32_t sb = smem_u32(fsm);
    const uint32_t sQh = sb, sQl = sb + F_QTILE * 2;
    const uint32_t kvbase = sb + 2 * F_QTILE * 2;

    // Prologue: Q tile + KV stage 0 (group), KV stage 1 (group)
    #pragma unroll
    for (int rep = 0; rep < 8; rep++) {
        int idx = tid + rep * 256;        // 0..2047
        int mat = idx >> 10;              // 0:Qhi 1:Qlo
        int row = (idx >> 3) & 127;
        int ch = idx & 7;
        const __nv_bfloat16* src = (mat ? qlo : qhi) +
            (size_t)(b * PS + q0 + row) * QKV_N + h * PHD + ch * 8;
        uint32_t dst = (mat ? sQl : sQh) + (row * F_LDS + ch * 8) * 2;
        CP_ASYNC16(dst, src);
    }
    flash_load_kv(qhi, qlo, kvbase, b, h, 0, tid);
    CP_ASYNC_COMMIT();
    const int ntiles = (q0 + 128) / 64;   // >= 2
    flash_load_kv(qhi, qlo, kvbase + 4 * F_KVT * 2, b, h, 64, tid);
    CP_ASYNC_COMMIT();

    uint32_t qfh[4][4], qfl[4][4];        // Q A-frags (4 k16 groups)
    float of[8][4];
    #pragma unroll
    for (int nt = 0; nt < 8; nt++)
        #pragma unroll
        for (int r = 0; r < 4; r++) of[nt][r] = 0.0f;
    float m_a = -1e30f, m_b = -1e30f, l_a = 0.0f, l_b = 0.0f;

    const uint32_t roff = (lane & 15) * (F_LDS * 2);
    const uint32_t coff = (lane >> 4) * 8 * 2;

    for (int i = 0; i < ntiles; i++) {
        CP_ASYNC_WAIT1();
        __syncthreads();

        if (i == 0) {                     // Q frags once (stage0 group incl. Q)
            #pragma unroll
            for (int g = 0; g < 4; g++) {
                uint32_t ra = wm * (F_LDS * 2) + roff + coff + g * 32;  // col g*16
                ldsm_x4(qfh[g], sQh + ra);
                ldsm_x4(qfl[g], sQl + ra);
            }
        }
        if (i + 2 < ntiles)
            flash_load_kv(qhi, qlo, kvbase + ((i + 2) % 3) * 4 * F_KVT * 2,
                          b, h, (i + 2) * 64, tid);
        CP_ASYNC_COMMIT();

        const uint32_t stg = kvbase + (i % 3) * 4 * F_KVT * 2;
        const uint32_t sKh = stg, sKl = stg + F_KVT * 2;
        const uint32_t sVh = stg + 2 * F_KVT * 2, sVl = stg + 3 * F_KVT * 2;
        const int j0 = i * 64;

        // ---- scores S = Q @ K^T (3-term split) ----
        float sf[8][4];
        #pragma unroll
        for (int nt = 0; nt < 8; nt++)
            #pragma unroll
            for (int r = 0; r < 4; r++) sf[nt][r] = 0.0f;

        #pragma unroll
        for (int kk = 0; kk < 4; kk++) {
            uint32_t ck = coff + kk * 32;             // hd col = kk*16 + ...
            uint32_t bkh[8][2], bkl[8][2];
            #pragma unroll
            for (int np = 0; np < 4; np++) {          // kv n16 groups
                uint32_t rb = (np * 16) * (F_LDS * 2) + roff + ck;
                uint32_t t[4];
                ldsm_x4(t, sKh + rb);
                bkh[2 * np][0] = t[0]; bkh[2 * np][1] = t[2];
                bkh[2 * np + 1][0] = t[1]; bkh[2 * np + 1][1] = t[3];
                ldsm_x4(t, sKl + rb);
                bkl[2 * np][0] = t[0]; bkl[2 * np][1] = t[2];
                bkl[2 * np + 1][0] = t[1]; bkl[2 * np + 1][1] = t[3];
            }
            #pragma unroll
            for (int nt = 0; nt < 8; nt++) {
                mma_bf16(sf[nt], qfh[kk], bkh[nt][0], bkh[nt][1]);
                mma_bf16(sf[nt], qfh[kk], bkl[nt][0], bkl[nt][1]);
                mma_bf16(sf[nt], qfl[kk], bkh[nt][0], bkh[nt][1]);
            }
        }

        // ---- causal mask (only the last two tiles touch the diagonal) ----
        const int r_a = q0 + wm + (lane >> 2);
        if (i >= ntiles - 2) {
            #pragma unroll
            for (int nt = 0; nt < 8; nt++) {
                int c0 = j0 + nt * 8 + (lane & 3) * 2;
                if (c0 > r_a)     sf[nt][0] = -1e30f;
                if (c0 + 1 > r_a) sf[nt][1] = -1e30f;
                if (c0 > r_a + 8)     sf[nt][2] = -1e30f;
                if (c0 + 1 > r_a + 8) sf[nt][3] = -1e30f;
            }
        }

        // ---- online softmax (base-2 domain; QSCALE folded into Q) ----
        float tm_a = -1e30f, tm_b = -1e30f;
        #pragma unroll
        for (int nt = 0; nt < 8; nt++) {
            tm_a = fmaxf(tm_a, fmaxf(sf[nt][0], sf[nt][1]));
            tm_b = fmaxf(tm_b, fmaxf(sf[nt][2], sf[nt][3]));
        }
        tm_a = fmaxf(tm_a, __shfl_xor_sync(0xffffffffu, tm_a, 1));
        tm_a = fmaxf(tm_a, __shfl_xor_sync(0xffffffffu, tm_a, 2));
        tm_b = fmaxf(tm_b, __shfl_xor_sync(0xffffffffu, tm_b, 1));
        tm_b = fmaxf(tm_b, __shfl_xor_sync(0xffffffffu, tm_b, 2));

        float mn_a = fmaxf(m_a, tm_a), mn_b = fmaxf(m_b, tm_b);
        float alpha_a = exp2f(m_a - mn_a), alpha_b = exp2f(m_b - mn_b);
        m_a = mn_a; m_b = mn_b;
        l_a *= alpha_a; l_b *= alpha_b;
        #pragma unroll
        for (int nt = 0; nt < 8; nt++) {
            of[nt][0] *= alpha_a; of[nt][1] *= alpha_a;
            of[nt][2] *= alpha_b; of[nt][3] *= alpha_b;
        }

        float rs_a = 0.0f, rs_b = 0.0f;
        #pragma unroll
        for (int nt = 0; nt < 8; nt++) {
            sf[nt][0] = exp2f(sf[nt][0] - m_a);
            sf[nt][1] = exp2f(sf[nt][1] - m_a);
            sf[nt][2] = exp2f(sf[nt][2] - m_b);
            sf[nt][3] = exp2f(sf[nt][3] - m_b);
            rs_a += sf[nt][0] + sf[nt][1];
            rs_b += sf[nt][2] + sf[nt][3];
        }
        rs_a += __shfl_xor_sync(0xffffffffu, rs_a, 1);
        rs_a += __shfl_xor_sync(0xffffffffu, rs_a, 2);
        rs_b += __shfl_xor_sync(0xffffffffu, rs_b, 1);
        rs_b += __shfl_xor_sync(0xffffffffu, rs_b, 2);
        l_a += rs_a; l_b += rs_b;

        // ---- pack P into A-frags (hi + residual lo) ----
        uint32_t pfh[4][4], pfl[4][4];
        #pragma unroll
        for (int g = 0; g < 4; g++) {
            #pragma unroll
            for (int q = 0; q < 4; q++) {
                int f = 2 * g + (q >> 1);
                int e = (q & 1) * 2;
                float p0 = sf[f][e], p1 = sf[f][e + 1];
                uint32_t u = pack_bf16x2(p0, p1);
                pfh[g][q] = u;
                float h0 = __uint_as_float(u << 16);
                float h1 = __uint_as_float(u & 0xffff0000u);
                pfl[g][q] = pack_bf16x2(p0 - h0, p1 - h1);
            }
        }

        // ---- O += P @ V (3-term split), V via ldmatrix.trans ----
        #pragma unroll
        for (int g = 0; g < 4; g++) {                 // kv k16 groups
            uint32_t bvh[8][2], bvl[8][2];
            #pragma unroll
            for (int hh = 0; hh < 4; hh++) {          // hd n16 groups
                uint32_t rb = (g * 16) * (F_LDS * 2) + roff + coff + hh * 32;
                uint32_t t[4];
                ldsm_x4_t(t, sVh + rb);
                bvh[2 * hh][0] = t[0]; bvh[2 * hh][1] = t[1];
                bvh[2 * hh + 1][0] = t[2]; bvh[2 * hh + 1][1] = t[3];
                ldsm_x4_t(t, sVl + rb);
                bvl[2 * hh][0] = t[0]; bvl[2 * hh][1] = t[1];
                bvl[2 * hh + 1][0] = t[2]; bvl[2 * hh + 1][1] = t[3];
            }
            #pragma unroll
            for (int nt = 0; nt < 8; nt++) {
                mma_bf16(of[nt], pfh[g], bvh[nt][0], bvh[nt][1]);
                mma_bf16(of[nt], pfh[g], bvl[nt][0], bvl[nt][1]);
                mma_bf16(of[nt], pfl[g], bvh[nt][0], bvh[nt][1]);
            }
        }
        __syncthreads();
    }

    // ---- epilogue: normalize, split to bf16 hi/lo, store ----
    const float inva = 1.0f / l_a, invb = 1.0f / l_b;
    const size_t row_a = (size_t)(b * PS + q0 + wm + (lane >> 2));
    #pragma unroll
    for (int nt = 0; nt < 8; nt++) {
        int col = h * PHD + nt * 8 + (lane & 3) * 2;
        float v0 = of[nt][0] * inva, v1 = of[nt][1] * inva;
        float v2 = of[nt][2] * invb, v3 = of[nt][3] * invb;
        __nv_bfloat16 h0 = __float2bfloat16(v0), h1 = __float2bfloat16(v1);
        __nv_bfloat16 h2 = __float2bfloat16(v2), h3 = __float2bfloat16(v3);
        __nv_bfloat16 e0 = __float2bfloat16(v0 - __bfloat162float(h0));
        __nv_bfloat16 e1 = __float2bfloat16(v1 - __bfloat162float(h1));
        __nv_bfloat16 e2 = __float2bfloat16(v2 - __bfloat162float(h2));
        __nv_bfloat16 e3 = __float2bfloat16(v3 - __bfloat162float(h3));
        *reinterpret_cast<__nv_bfloat162*>(out_hi + row_a * PD + col) = __nv_bfloat162(h0, h1);
        *reinterpret_cast<__nv_bfloat162*>(out_hi + (row_a + 8) * PD + col) = __nv_bfloat162(h2, h3);
        *reinterpret_cast<__nv_bfloat162*>(out_lo + row_a * PD + col) = __nv_bfloat162(e0, e1);
        *reinterpret_cast<__nv_bfloat162*>(out_lo + (row_a + 8) * PD + col) = __nv_bfloat162(e2, e3);
    }
}

// ---------------------------------------------------------------------------
// Launch
// ---------------------------------------------------------------------------
extern "C" void kernel_launch(void* const* d_in, const int* in_sizes, int n_in,
                              void* d_out, int out_size)
{
    const float* x     = (const float*)d_in[0];
    const float* w_qkv = (const float*)d_in[1];
    const float* b_qkv = (const float*)d_in[2];
    const float* w_out = (const float*)d_in[3];
    const float* b_out = (const float*)d_in[4];
    float* out = (float*)d_out;

    __nv_bfloat16 *qkvhi, *qkvlo, *xhi, *xlo, *wqh, *wql, *woh, *wol, *ahi, *alo;
    cudaGetSymbolAddress((void**)&qkvhi, g_qkvhi);
    cudaGetSymbolAddress((void**)&qkvlo, g_qkvlo);
    cudaGetSymbolAddress((void**)&xhi, g_xhi);
    cudaGetSymbolAddress((void**)&xlo, g_xlo);
    cudaGetSymbolAddress((void**)&wqh, g_wqkvT_hi);
    cudaGetSymbolAddress((void**)&wql, g_wqkvT_lo);
    cudaGetSymbolAddress((void**)&woh, g_woutT_hi);
    cudaGetSymbolAddress((void**)&wol, g_woutT_lo);
    cudaGetSymbolAddress((void**)&ahi, g_ahi);
    cudaGetSymbolAddress((void**)&alo, g_alo);

    cudaFuncSetAttribute(gemm_mma_kernel<0>,
                         cudaFuncAttributeMaxDynamicSharedMemorySize, G_SMEM_BYTES);
    cudaFuncSetAttribute(gemm_mma_kernel<1>,
                         cudaFuncAttributeMaxDynamicSharedMemorySize, G_SMEM_BYTES);
    cudaFuncSetAttribute(flash_mma_kernel,
                         cudaFuncAttributeMaxDynamicSharedMemorySize, F_SMEM_BYTES);

    // Prep: split x; transpose+split weights
    {
        int n4 = M_ROWS * PD / 4;
        convert_split_kernel<<<(n4 + 255) / 256, 256>>>(x, xhi, xlo, n4);
        dim3 blk(32, 8);
        transpose_split_kernel<<<dim3(QKV_N / 32, PD / 32), blk>>>(w_qkv, wqh, wql, PD, QKV_N);
        transpose_split_kernel<<<dim3(PD / 32, PD / 32), blk>>>(w_out, woh, wol, PD, PD);
    }

    // 1) QKV projection -> bf16 hi/lo (Q columns pre-scaled by 0.125*log2e)
    {
        dim3 grid(QKV_N / G_BN, M_ROWS / G_BM);
        gemm_mma_kernel<1><<<grid, 256, G_SMEM_BYTES>>>(xhi, xlo, wqh, wql,
                                                        b_qkv, nullptr, qkvhi, qkvlo,
                                                        PD, QKV_N);
    }

    // 2) Tensor-core causal flash attention -> bf16 hi/lo
    {
        dim3 grid(PS / 128, PB * PH);             // (16, 64)
        flash_mma_kernel<<<grid, 256, F_SMEM_BYTES>>>(qkvhi, qkvlo, ahi, alo);
    }

    // 3) Output projection -> fp32 out
    {
        dim3 grid(PD / G_BN, M_ROWS / G_BM);
        gemm_mma_kernel<0><<<grid, 256, G_SMEM_BYTES>>>(ahi, alo, woh, wol,
                                                        b_out, out, nullptr, nullptr,
                                                        PD, PD);
    }
}